// round 1
// baseline (speedup 1.0000x reference)
#include <cuda_runtime.h>

#define NPIX 9216
#define LAB  21
#define HH   96
#define WW   96
#define RAD  9
#define KW   (2*RAD+1)

// ---- scratch (device globals: allocation-free kernel_launch) ----
__device__ float g_K[(size_t)NPIX * NPIX];   // 340 MB bilateral kernel matrix
__device__ float g_feats[NPIX * 5];
__device__ float g_nbi[NPIX];
__device__ float g_nsp[NPIX];
__device__ float g_kw[KW];
__device__ float g_Q[LAB * NPIX];            // current Q, [L][H*W]
__device__ float g_tmp[LAB * NPIX];          // y-conv intermediate
__device__ float g_V[NPIX * LAB];            // nbi * Q, [N][L]
__device__ float g_C[NPIX * LAB];            // K @ V,   [N][L]

// ---------------------------------------------------------------------------
// Prep: gaussian weights, spatial normalizer nsp, bilateral features
// ---------------------------------------------------------------------------
__global__ void k_prep(const float* __restrict__ I) {
    int n = blockIdx.x * blockDim.x + threadIdx.x;
    if (n >= NPIX) return;
    int y = n / WW, x = n % WW;

    if (n < KW) {
        float d = (float)(n - RAD) / 3.0f;
        g_kw[n] = expf(-0.5f * d * d);
    }

    float sy = 0.f, sx = 0.f;
    #pragma unroll
    for (int d = -RAD; d <= RAD; d++) {
        float t = (float)d / 3.0f;
        float w = expf(-0.5f * t * t);
        if ((unsigned)(y + d) < HH) sy += w;
        if ((unsigned)(x + d) < WW) sx += w;
    }
    g_nsp[n] = rsqrtf(sy * sx);

    g_feats[n * 5 + 0] = (float)x / 80.0f;     // BI_X_STD
    g_feats[n * 5 + 1] = (float)y / 80.0f;     // BI_Y_STD
    g_feats[n * 5 + 2] = I[0 * NPIX + n] / 13.0f;
    g_feats[n * 5 + 3] = I[1 * NPIX + n] / 13.0f;
    g_feats[n * 5 + 4] = I[2 * NPIX + n] / 13.0f;
}

// ---------------------------------------------------------------------------
// Build K (and row sums -> nbi). 8 rows per 256-thread block (1 row / warp),
// feature chunks staged in SMEM so L2 feats traffic is /8.
// ---------------------------------------------------------------------------
#define KCHUNK 1536
__global__ void k_buildK() {
    __shared__ float fs[KCHUNK * 5];   // 30720 B
    int warp = threadIdx.x >> 5, lane = threadIdx.x & 31;
    int row = blockIdx.x * 8 + warp;

    float fr[5];
    #pragma unroll
    for (int j = 0; j < 5; j++) fr[j] = g_feats[row * 5 + j];

    float sum = 0.f;
    for (int c0 = 0; c0 < NPIX; c0 += KCHUNK) {
        __syncthreads();
        for (int i = threadIdx.x; i < KCHUNK * 5; i += blockDim.x)
            fs[i] = g_feats[c0 * 5 + i];
        __syncthreads();
        float* krow = g_K + (size_t)row * NPIX + c0;
        for (int m = lane; m < KCHUNK; m += 32) {
            float d = 0.f;
            #pragma unroll
            for (int j = 0; j < 5; j++) {
                float t = fr[j] - fs[m * 5 + j];
                d += t * t;
            }
            float k = __expf(-0.5f * d);
            krow[m] = k;
            sum += k;
        }
    }
    #pragma unroll
    for (int off = 16; off; off >>= 1)
        sum += __shfl_xor_sync(0xffffffffu, sum, off);
    if (lane == 0) g_nbi[row] = rsqrtf(sum);
}

// ---------------------------------------------------------------------------
// Q0 = softmax(-U) over labels; also seed V = nbi * Q
// ---------------------------------------------------------------------------
__global__ void k_q0(const float* __restrict__ U) {
    int n = blockIdx.x * blockDim.x + threadIdx.x;
    if (n >= NPIX) return;
    float lg[LAB];
    float mx = -1e30f;
    #pragma unroll
    for (int l = 0; l < LAB; l++) {
        float v = -U[l * NPIX + n];
        lg[l] = v;
        mx = fmaxf(mx, v);
    }
    float se = 0.f;
    #pragma unroll
    for (int l = 0; l < LAB; l++) { lg[l] = __expf(lg[l] - mx); se += lg[l]; }
    float inv = 1.0f / se;
    float nb = g_nbi[n];
    #pragma unroll
    for (int l = 0; l < LAB; l++) {
        float q = lg[l] * inv;
        g_Q[l * NPIX + n] = q;
        g_V[n * LAB + l] = nb * q;
    }
}

// ---------------------------------------------------------------------------
// Spatial pass 1: y-direction conv of (nsp * Q), zero padding
// ---------------------------------------------------------------------------
__global__ void k_pass1() {
    int t = blockIdx.x * blockDim.x + threadIdx.x;
    if (t >= LAB * NPIX) return;
    int l = t / NPIX, n = t - l * NPIX;
    int y = n / WW, x = n - y * WW;
    float s = 0.f;
    #pragma unroll
    for (int d = -RAD; d <= RAD; d++) {
        int yy = y + d;
        if ((unsigned)yy < HH) {
            int m = yy * WW + x;
            s += g_kw[d + RAD] * g_nsp[m] * g_Q[l * NPIX + m];
        }
    }
    g_tmp[t] = s;
}

// ---------------------------------------------------------------------------
// Bilateral: C = K @ V.  256 threads = 8 warps, 4 rows per warp (32 rows/blk).
// V chunk staged in SMEM; K loads coalesced per warp; 4x reuse of each LDS.
// ---------------------------------------------------------------------------
#define MCHUNK 512
__global__ void __launch_bounds__(256) k_bilateral() {
    __shared__ float Vs[MCHUNK * LAB];  // 43008 B
    int warp = threadIdx.x >> 5, lane = threadIdx.x & 31;
    int rowBase = (blockIdx.x * 8 + warp) * 4;

    float acc[4][LAB];
    #pragma unroll
    for (int r = 0; r < 4; r++)
        #pragma unroll
        for (int l = 0; l < LAB; l++) acc[r][l] = 0.f;

    const float* K0 = g_K + (size_t)(rowBase + 0) * NPIX;
    const float* K1 = g_K + (size_t)(rowBase + 1) * NPIX;
    const float* K2 = g_K + (size_t)(rowBase + 2) * NPIX;
    const float* K3 = g_K + (size_t)(rowBase + 3) * NPIX;

    for (int c0 = 0; c0 < NPIX; c0 += MCHUNK) {
        __syncthreads();
        for (int i = threadIdx.x; i < MCHUNK * LAB; i += blockDim.x)
            Vs[i] = g_V[c0 * LAB + i];
        __syncthreads();
        #pragma unroll 4
        for (int mi = 0; mi < MCHUNK; mi += 32) {
            int m = mi + lane;
            float k0 = K0[c0 + m];
            float k1 = K1[c0 + m];
            float k2 = K2[c0 + m];
            float k3 = K3[c0 + m];
            const float* vp = &Vs[m * LAB];
            #pragma unroll
            for (int l = 0; l < LAB; l++) {
                float v = vp[l];
                acc[0][l] += k0 * v;
                acc[1][l] += k1 * v;
                acc[2][l] += k2 * v;
                acc[3][l] += k3 * v;
            }
        }
    }

    #pragma unroll
    for (int r = 0; r < 4; r++) {
        #pragma unroll
        for (int l = 0; l < LAB; l++) {
            float v = acc[r][l];
            #pragma unroll
            for (int off = 16; off; off >>= 1)
                v += __shfl_xor_sync(0xffffffffu, v, off);
            if (lane == 0) g_C[(rowBase + r) * LAB + l] = v;
        }
    }
}

// ---------------------------------------------------------------------------
// Combine: x-direction conv of tmp, add unary + messages, softmax -> Q, V
// ---------------------------------------------------------------------------
__global__ void k_combine(const float* __restrict__ U, float* __restrict__ out,
                          int writeOut) {
    int n = blockIdx.x * blockDim.x + threadIdx.x;
    if (n >= NPIX) return;
    int y = n / WW, x = n - y * WW;
    float nsp = g_nsp[n];
    float nbi = g_nbi[n];

    float lg[LAB];
    float mx = -1e30f;
    #pragma unroll
    for (int l = 0; l < LAB; l++) {
        float s = 0.f;
        #pragma unroll
        for (int d = -RAD; d <= RAD; d++) {
            int xx = x + d;
            if ((unsigned)xx < WW)
                s += g_kw[d + RAD] * g_tmp[l * NPIX + y * WW + xx];
        }
        float v = -U[l * NPIX + n] + 3.0f * nsp * s + 10.0f * nbi * g_C[n * LAB + l];
        lg[l] = v;
        mx = fmaxf(mx, v);
    }
    float se = 0.f;
    #pragma unroll
    for (int l = 0; l < LAB; l++) { lg[l] = __expf(lg[l] - mx); se += lg[l]; }
    float inv = 1.0f / se;
    #pragma unroll
    for (int l = 0; l < LAB; l++) {
        float q = lg[l] * inv;
        g_Q[l * NPIX + n] = q;
        g_V[n * LAB + l] = nbi * q;
        if (writeOut) out[l * NPIX + n] = q;
    }
}

// ---------------------------------------------------------------------------
extern "C" void kernel_launch(void* const* d_in, const int* in_sizes, int n_in,
                              void* d_out, int out_size) {
    const float* U = (const float*)d_in[0];   // [1,21,96,96]
    const float* I = (const float*)d_in[1];   // [1,3,96,96]
    float* out = (float*)d_out;               // [1,21,96,96]

    k_prep<<<36, 256>>>(I);
    k_buildK<<<NPIX / 8, 256>>>();
    k_q0<<<36, 256>>>(U);

    for (int it = 0; it < 10; it++) {
        k_pass1<<<(LAB * NPIX + 255) / 256, 256>>>();
        k_bilateral<<<NPIX / 32, 256>>>();
        k_combine<<<36, 256>>>(U, out, it == 9 ? 1 : 0);
    }
}

// round 3
// speedup vs baseline: 3.4394x; 3.4394x over previous
#include <cuda_runtime.h>
#include <cuda_bf16.h>
#include <cstdint>

#define NPIX 9216
#define LAB  21
#define HH   96
#define WW   96
#define RAD  9
#define KWD  (2*RAD+1)
#define NBLK 72                 // 9216 / 128

// ---- scratch (device globals: allocation-free kernel_launch) ----
__device__ __nv_bfloat16 g_Kb[(size_t)NPIX * NPIX];   // 170 MB bilateral kernel (bf16)
__device__ float g_feats[NPIX * 5];
__device__ float g_rowsum[NPIX];
__device__ float g_nbi[NPIX];
__device__ float g_nsp[NPIX];
__device__ float g_kw[KWD];
__device__ float g_Q[LAB * NPIX];                     // [L][N]
__device__ float g_tmp[LAB * NPIX];                   // y-conv intermediate
__device__ __nv_bfloat16 g_VT[32 * NPIX];             // (nbi*Q)^T, rows 21..31 zero
__device__ float g_C[NPIX * LAB];                     // K @ V, [N][L]

// ===========================================================================
// helpers
// ===========================================================================
__device__ __forceinline__ uint32_t smem_u32(const void* p) {
    uint32_t a;
    asm("{ .reg .u64 t; cvta.to.shared.u64 t, %1; cvt.u32.u64 %0, t; }" : "=r"(a) : "l"(p));
    return a;
}
__device__ __forceinline__ uint32_t swz(uint32_t off) {   // 8x128B xor swizzle
    return off ^ ((off >> 3) & 0x70);
}
__device__ __forceinline__ void cp16(uint32_t dst, const void* src) {
    asm volatile("cp.async.cg.shared.global [%0], [%1], 16;" :: "r"(dst), "l"(src) : "memory");
}

// ===========================================================================
// Prep: gaussian weights, spatial normalizer nsp, features, zero rowsum/VT pad
// ===========================================================================
__global__ void k_prep(const float* __restrict__ I) {
    int n = blockIdx.x * blockDim.x + threadIdx.x;
    if (n >= NPIX) return;
    int y = n / WW, x = n % WW;

    if (n < KWD) {
        float d = (float)(n - RAD) / 3.0f;
        g_kw[n] = expf(-0.5f * d * d);
    }
    float sy = 0.f, sx = 0.f;
    #pragma unroll
    for (int d = -RAD; d <= RAD; d++) {
        float t = (float)d / 3.0f;
        float w = expf(-0.5f * t * t);
        if ((unsigned)(y + d) < HH) sy += w;
        if ((unsigned)(x + d) < WW) sx += w;
    }
    g_nsp[n] = rsqrtf(sy * sx);
    g_rowsum[n] = 0.f;

    g_feats[n * 5 + 0] = (float)x / 80.0f;
    g_feats[n * 5 + 1] = (float)y / 80.0f;
    g_feats[n * 5 + 2] = I[0 * NPIX + n] / 13.0f;
    g_feats[n * 5 + 3] = I[1 * NPIX + n] / 13.0f;
    g_feats[n * 5 + 4] = I[2 * NPIX + n] / 13.0f;

    __nv_bfloat16 z = __float2bfloat16(0.f);
    #pragma unroll
    for (int l = LAB; l < 32; l++) g_VT[l * NPIX + n] = z;
}

// ===========================================================================
// Build K (bf16) exploiting symmetry: one block per upper-tri 128x128 tile.
// Writes tile + transposed tile; row sums accumulated via atomics.
// ===========================================================================
#define TSTR 136   // tile row stride in elements (16B-aligned, conflict-light)
__global__ void __launch_bounds__(256) k_buildK() {
    __shared__ float fA[128 * 5];
    __shared__ float fB[128 * 5];
    __shared__ __align__(16) unsigned short tile[128 * TSTR];

    int id = blockIdx.x;
    // map id -> (bi, bj), bi <= bj
    int bi;
    {
        float b = 2.f * NBLK + 1.f;
        bi = (int)((b - sqrtf(b * b - 8.f * (float)id)) * 0.5f);
        if (bi < 0) bi = 0;
        if (bi > NBLK - 1) bi = NBLK - 1;
        while (bi * NBLK - bi * (bi - 1) / 2 > id) bi--;
        while ((bi + 1) * NBLK - (bi + 1) * bi / 2 <= id) bi++;
    }
    int bj = bi + (id - (bi * NBLK - bi * (bi - 1) / 2));

    int tid = threadIdx.x;
    for (int i = tid; i < 640; i += 256) {
        fA[i] = g_feats[bi * 640 + i];
        fB[i] = g_feats[bj * 640 + i];
    }
    __syncthreads();

    int r = tid >> 1;
    int cbase = (tid & 1) * 64;
    float f0 = fA[r * 5 + 0], f1 = fA[r * 5 + 1], f2 = fA[r * 5 + 2];
    float f3 = fA[r * 5 + 3], f4 = fA[r * 5 + 4];

    float sum = 0.f;
    #pragma unroll 4
    for (int c = 0; c < 64; c++) {
        const float* fb = &fB[(cbase + c) * 5];
        float t0 = f0 - fb[0], t1 = f1 - fb[1], t2 = f2 - fb[2];
        float t3 = f3 - fb[3], t4 = f4 - fb[4];
        float d = t0 * t0 + t1 * t1 + t2 * t2 + t3 * t3 + t4 * t4;
        float k = __expf(-0.5f * d);
        sum += k;
        tile[r * TSTR + cbase + c] = __bfloat16_as_ushort(__float2bfloat16_rn(k));
    }
    // pair-combine row partial (lanes tid, tid^1 share r)
    sum += __shfl_xor_sync(0xffffffffu, sum, 1);
    if ((tid & 1) == 0) atomicAdd(&g_rowsum[bi * 128 + r], sum);
    __syncthreads();

    unsigned short* gK = (unsigned short*)g_Kb;

    // direct tile write (coalesced uint4)
    for (int o = tid * 8; o < 16384; o += 2048) {
        int rr = o >> 7, cc = o & 127;
        uint4 v = *(const uint4*)&tile[rr * TSTR + cc];
        *(uint4*)&gK[(size_t)(bi * 128 + rr) * NPIX + bj * 128 + cc] = v;
    }

    if (bi != bj) {
        // transposed tile write
        for (int o = tid * 8; o < 16384; o += 2048) {
            int cc = o >> 7, rb = o & 127;
            unsigned short v[8];
            #pragma unroll
            for (int k = 0; k < 8; k++) v[k] = tile[(rb + k) * TSTR + cc];
            uint4 u;
            u.x = (uint32_t)v[0] | ((uint32_t)v[1] << 16);
            u.y = (uint32_t)v[2] | ((uint32_t)v[3] << 16);
            u.z = (uint32_t)v[4] | ((uint32_t)v[5] << 16);
            u.w = (uint32_t)v[6] | ((uint32_t)v[7] << 16);
            *(uint4*)&gK[(size_t)(bj * 128 + cc) * NPIX + bi * 128 + rb] = u;
        }
        // column sums -> row sums of bj block
        if (tid < 128) {
            float s = 0.f;
            #pragma unroll 4
            for (int rr = 0; rr < 128; rr++)
                s += __bfloat162float(__ushort_as_bfloat16(tile[rr * TSTR + tid]));
            atomicAdd(&g_rowsum[bj * 128 + tid], s);
        }
    }
}

// ===========================================================================
// Q0 = softmax(-U); nbi = rsqrt(rowsum); seed VT = (nbi*Q)^T in bf16
// ===========================================================================
__global__ void k_q0(const float* __restrict__ U) {
    int n = blockIdx.x * blockDim.x + threadIdx.x;
    if (n >= NPIX) return;
    float nb = rsqrtf(g_rowsum[n]);
    g_nbi[n] = nb;
    float lg[LAB];
    float mx = -1e30f;
    #pragma unroll
    for (int l = 0; l < LAB; l++) {
        float v = -U[l * NPIX + n];
        lg[l] = v; mx = fmaxf(mx, v);
    }
    float se = 0.f;
    #pragma unroll
    for (int l = 0; l < LAB; l++) { lg[l] = __expf(lg[l] - mx); se += lg[l]; }
    float inv = 1.0f / se;
    #pragma unroll
    for (int l = 0; l < LAB; l++) {
        float q = lg[l] * inv;
        g_Q[l * NPIX + n] = q;
        g_VT[l * NPIX + n] = __float2bfloat16_rn(nb * q);
    }
}

// ===========================================================================
// Spatial pass 1: y-direction conv of (nsp * Q), zero padding
// ===========================================================================
__global__ void k_pass1() {
    int t = blockIdx.x * blockDim.x + threadIdx.x;
    if (t >= LAB * NPIX) return;
    int l = t / NPIX, n = t - l * NPIX;
    int y = n / WW, x = n - y * WW;
    float s = 0.f;
    #pragma unroll
    for (int d = -RAD; d <= RAD; d++) {
        int yy = y + d;
        if ((unsigned)yy < HH) {
            int m = yy * WW + x;
            s += g_kw[d + RAD] * g_nsp[m] * g_Q[l * NPIX + m];
        }
    }
    g_tmp[t] = s;
}

// ===========================================================================
// Bilateral GEMM via mma.sync bf16 HMMA:
// C[9216,24] = Kb @ VT^T.  144 CTAs x M=64 rows, 4 warps x 16 rows.
// k-chunks of 64; 6-stage cp.async pipeline, xor-swizzled tiles.
// ===========================================================================
#define NS     6
#define NCH    144
#define STAGE  11264          // 8192 (A: 64x128B) + 3072 (B: 24x128B)
#define SMEM_BIL (NS * STAGE)

__device__ __forceinline__ void bil_load_stage(uint32_t base, int s,
                                               int rowBase, int c0, int tid) {
    uint32_t sA = base + s * STAGE;
    uint32_t sB = sA + 8192;
    #pragma unroll
    for (int it = 0; it < 6; it++) {
        int u = tid + it * 128;             // 704 16B units total
        if (u < 512) {
            int r = u >> 3, j = u & 7;
            cp16(sA + swz(r * 128 + j * 16),
                 g_Kb + (size_t)(rowBase + r) * NPIX + c0 + j * 8);
        } else if (u < 704) {
            int v = u - 512;
            int n = v >> 3, j = v & 7;
            cp16(sB + swz(n * 128 + j * 16),
                 g_VT + (size_t)n * NPIX + c0 + j * 8);
        }
    }
    asm volatile("cp.async.commit_group;" ::: "memory");
}

__global__ void __launch_bounds__(128, 1) k_bil() {
    extern __shared__ char smem[];
    uint32_t base = smem_u32(smem);
    int tid = threadIdx.x;
    int wid = tid >> 5, lane = tid & 31;
    int rowBase = blockIdx.x * 64;

    // lane geometry for ldmatrix
    int ar = (lane & 7) + ((lane >> 3) & 1) * 8;     // A row within 16
    int au = (lane >> 4) & 1;                        // A extra 16B unit
    int bl = lane & 15;
    int brr = bl & 7;                                // B row within 8
    int bu = (bl >> 3) & 1;                          // B extra unit

    float d[3][4];
    #pragma unroll
    for (int t = 0; t < 3; t++)
        #pragma unroll
        for (int k = 0; k < 4; k++) d[t][k] = 0.f;

    #pragma unroll
    for (int j = 0; j < NS - 1; j++)
        bil_load_stage(base, j, rowBase, j * 64, tid);

    for (int i = 0; i < NCH; i++) {
        int rem = (NCH - 1) - i;
        if      (rem >= 4) asm volatile("cp.async.wait_group 4;" ::: "memory");
        else if (rem == 3) asm volatile("cp.async.wait_group 3;" ::: "memory");
        else if (rem == 2) asm volatile("cp.async.wait_group 2;" ::: "memory");
        else if (rem == 1) asm volatile("cp.async.wait_group 1;" ::: "memory");
        else               asm volatile("cp.async.wait_group 0;" ::: "memory");
        __syncthreads();

        uint32_t sA = base + (i % NS) * STAGE;
        uint32_t sB = sA + 8192;

        #pragma unroll
        for (int kk = 0; kk < 4; kk++) {            // 4 k16-steps per 64-chunk
            uint32_t a0, a1, a2, a3;
            uint32_t aoff = (uint32_t)((wid * 16 + ar) * 128 + (kk * 2 + au) * 16);
            asm volatile("ldmatrix.sync.aligned.m8n8.x4.shared.b16 {%0,%1,%2,%3}, [%4];"
                         : "=r"(a0), "=r"(a1), "=r"(a2), "=r"(a3)
                         : "r"(sA + swz(aoff)));
            #pragma unroll
            for (int t = 0; t < 3; t++) {
                uint32_t b0, b1;
                uint32_t boff = (uint32_t)((t * 8 + brr) * 128 + (kk * 2 + bu) * 16);
                asm volatile("ldmatrix.sync.aligned.m8n8.x2.shared.b16 {%0,%1}, [%2];"
                             : "=r"(b0), "=r"(b1)
                             : "r"(sB + swz(boff)));
                asm volatile("mma.sync.aligned.m16n8k16.row.col.f32.bf16.bf16.f32 "
                             "{%0,%1,%2,%3}, {%4,%5,%6,%7}, {%8,%9}, {%0,%1,%2,%3};"
                             : "+f"(d[t][0]), "+f"(d[t][1]), "+f"(d[t][2]), "+f"(d[t][3])
                             : "r"(a0), "r"(a1), "r"(a2), "r"(a3), "r"(b0), "r"(b1));
            }
        }
        __syncthreads();

        int n = i + NS - 1;
        if (n < NCH)
            bil_load_stage(base, n % NS, rowBase, n * 64, tid);
    }

    // epilogue: write C rows (fragment layout of m16n8 accumulators)
    int row = rowBase + wid * 16 + (lane >> 2);
    #pragma unroll
    for (int t = 0; t < 3; t++) {
        int col = t * 8 + (lane & 3) * 2;
        if (col < LAB)     g_C[row * LAB + col]           = d[t][0];
        if (col + 1 < LAB) g_C[row * LAB + col + 1]       = d[t][1];
        if (col < LAB)     g_C[(row + 8) * LAB + col]     = d[t][2];
        if (col + 1 < LAB) g_C[(row + 8) * LAB + col + 1] = d[t][3];
    }
}

// ===========================================================================
// Combine: x-conv of tmp, add unary + messages, softmax -> Q, VT
// ===========================================================================
__global__ void k_combine(const float* __restrict__ U, float* __restrict__ out,
                          int writeOut) {
    int n = blockIdx.x * blockDim.x + threadIdx.x;
    if (n >= NPIX) return;
    int y = n / WW, x = n - y * WW;
    float nsp = g_nsp[n];
    float nbi = g_nbi[n];

    float lg[LAB];
    float mx = -1e30f;
    #pragma unroll
    for (int l = 0; l < LAB; l++) {
        float s = 0.f;
        #pragma unroll
        for (int d = -RAD; d <= RAD; d++) {
            int xx = x + d;
            if ((unsigned)xx < WW)
                s += g_kw[d + RAD] * g_tmp[l * NPIX + y * WW + xx];
        }
        float v = -U[l * NPIX + n] + 3.0f * nsp * s + 10.0f * nbi * g_C[n * LAB + l];
        lg[l] = v; mx = fmaxf(mx, v);
    }
    float se = 0.f;
    #pragma unroll
    for (int l = 0; l < LAB; l++) { lg[l] = __expf(lg[l] - mx); se += lg[l]; }
    float inv = 1.0f / se;
    #pragma unroll
    for (int l = 0; l < LAB; l++) {
        float q = lg[l] * inv;
        g_Q[l * NPIX + n] = q;
        g_VT[l * NPIX + n] = __float2bfloat16_rn(nbi * q);
        if (writeOut) out[l * NPIX + n] = q;
    }
}

// ===========================================================================
extern "C" void kernel_launch(void* const* d_in, const int* in_sizes, int n_in,
                              void* d_out, int out_size) {
    const float* U = (const float*)d_in[0];   // [1,21,96,96]
    const float* I = (const float*)d_in[1];   // [1,3,96,96]
    float* out = (float*)d_out;               // [1,21,96,96]

    cudaFuncSetAttribute(k_bil, cudaFuncAttributeMaxDynamicSharedMemorySize, SMEM_BIL);

    k_prep<<<36, 256>>>(I);
    k_buildK<<<NBLK * (NBLK + 1) / 2, 256>>>();
    k_q0<<<36, 256>>>(U);

    for (int it = 0; it < 10; it++) {
        k_pass1<<<(LAB * NPIX + 255) / 256, 256>>>();
        k_bil<<<NPIX / 64, 128, SMEM_BIL>>>();
        k_combine<<<36, 256>>>(U, out, it == 9 ? 1 : 0);
    }
}

// round 4
// speedup vs baseline: 3.5393x; 1.0291x over previous
#include <cuda_runtime.h>
#include <cuda_fp16.h>
#include <cstdint>

#define NPIX 9216
#define LAB  21
#define HH   96
#define WW   96
#define RAD  9
#define KWD  (2*RAD+1)
#define NBLK 72                 // 9216 / 128

// ---- scratch (device globals: allocation-free kernel_launch) ----
__device__ __half g_Kh[(size_t)NPIX * NPIX];   // only upper-tri 128-tiles written (~85MB touched)
__device__ float g_feats[NPIX * 5];
__device__ float g_rowsum[NPIX];
__device__ float g_nbi[NPIX];
__device__ float g_nsp[NPIX];
__device__ float g_kw[KWD];
__device__ float g_Q[LAB * NPIX];              // [L][N]
__device__ float g_tmp[LAB * NPIX];            // y-conv intermediate
__device__ __half g_VT[32 * NPIX];             // (nbi*Q)^T, rows 21..31 zero
__device__ float g_C[NPIX * LAB];              // K @ V, [N][L]

// ===========================================================================
// helpers
// ===========================================================================
__device__ __forceinline__ uint32_t smem_u32(const void* p) {
    uint32_t a;
    asm("{ .reg .u64 t; cvta.to.shared.u64 t, %1; cvt.u32.u64 %0, t; }" : "=r"(a) : "l"(p));
    return a;
}
__device__ __forceinline__ uint32_t swz(uint32_t off) {   // 8x128B xor swizzle
    return off ^ ((off >> 3) & 0x70);
}
__device__ __forceinline__ void cp16(uint32_t dst, const void* src) {
    asm volatile("cp.async.cg.shared.global [%0], [%1], 16;" :: "r"(dst), "l"(src) : "memory");
}

// ===========================================================================
// Prep
// ===========================================================================
__global__ void k_prep(const float* __restrict__ I) {
    int n = blockIdx.x * blockDim.x + threadIdx.x;
    if (n >= NPIX) return;
    int y = n / WW, x = n % WW;

    if (n < KWD) {
        float d = (float)(n - RAD) / 3.0f;
        g_kw[n] = expf(-0.5f * d * d);
    }
    float sy = 0.f, sx = 0.f;
    #pragma unroll
    for (int d = -RAD; d <= RAD; d++) {
        float t = (float)d / 3.0f;
        float w = expf(-0.5f * t * t);
        if ((unsigned)(y + d) < HH) sy += w;
        if ((unsigned)(x + d) < WW) sx += w;
    }
    g_nsp[n] = rsqrtf(sy * sx);
    g_rowsum[n] = 0.f;

    g_feats[n * 5 + 0] = (float)x / 80.0f;
    g_feats[n * 5 + 1] = (float)y / 80.0f;
    g_feats[n * 5 + 2] = I[0 * NPIX + n] / 13.0f;
    g_feats[n * 5 + 3] = I[1 * NPIX + n] / 13.0f;
    g_feats[n * 5 + 4] = I[2 * NPIX + n] / 13.0f;

    __half z = __float2half(0.f);
    #pragma unroll
    for (int l = LAB; l < 32; l++) g_VT[l * NPIX + n] = z;
}

// ===========================================================================
// Build K (fp16), upper-triangle 128x128 tiles only. Row sums via atomics
// (direct rows from fp32, column contribution of off-diag tiles from tile).
// ===========================================================================
#define TSTR 136
__global__ void __launch_bounds__(256) k_buildK() {
    __shared__ float fA[128 * 5];
    __shared__ float fB[128 * 5];
    __shared__ __align__(16) unsigned short tile[128 * TSTR];

    int id = blockIdx.x;
    int bi;
    {
        float b = 2.f * NBLK + 1.f;
        bi = (int)((b - sqrtf(b * b - 8.f * (float)id)) * 0.5f);
        if (bi < 0) bi = 0;
        if (bi > NBLK - 1) bi = NBLK - 1;
        while (bi * NBLK - bi * (bi - 1) / 2 > id) bi--;
        while ((bi + 1) * NBLK - (bi + 1) * bi / 2 <= id) bi++;
    }
    int bj = bi + (id - (bi * NBLK - bi * (bi - 1) / 2));

    int tid = threadIdx.x;
    for (int i = tid; i < 640; i += 256) {
        fA[i] = g_feats[bi * 640 + i];
        fB[i] = g_feats[bj * 640 + i];
    }
    __syncthreads();

    int r = tid >> 1;
    int cbase = (tid & 1) * 64;
    float f0 = fA[r * 5 + 0], f1 = fA[r * 5 + 1], f2 = fA[r * 5 + 2];
    float f3 = fA[r * 5 + 3], f4 = fA[r * 5 + 4];

    float sum = 0.f;
    #pragma unroll 4
    for (int c = 0; c < 64; c++) {
        const float* fb = &fB[(cbase + c) * 5];
        float t0 = f0 - fb[0], t1 = f1 - fb[1], t2 = f2 - fb[2];
        float t3 = f3 - fb[3], t4 = f4 - fb[4];
        float d = t0 * t0 + t1 * t1 + t2 * t2 + t3 * t3 + t4 * t4;
        float k = __expf(-0.5f * d);
        sum += k;
        tile[r * TSTR + cbase + c] = __half_as_ushort(__float2half_rn(k));
    }
    sum += __shfl_xor_sync(0xffffffffu, sum, 1);
    if ((tid & 1) == 0) atomicAdd(&g_rowsum[bi * 128 + r], sum);
    __syncthreads();

    unsigned short* gK = (unsigned short*)g_Kh;

    // direct (upper-tri) tile write, coalesced uint4
    for (int o = tid * 8; o < 16384; o += 2048) {
        int rr = o >> 7, cc = o & 127;
        uint4 v = *(const uint4*)&tile[rr * TSTR + cc];
        *(uint4*)&gK[(size_t)(bi * 128 + rr) * NPIX + bj * 128 + cc] = v;
    }

    if (bi != bj) {
        // column sums contribute to bj rows (symmetry); NO transposed write
        if (tid < 128) {
            float s = 0.f;
            #pragma unroll 4
            for (int rr = 0; rr < 128; rr++)
                s += __half2float(__ushort_as_half(tile[rr * TSTR + tid]));
            atomicAdd(&g_rowsum[bj * 128 + tid], s);
        }
    }
}

// ===========================================================================
// Q0 = softmax(-U); nbi; seed VT
// ===========================================================================
__global__ void k_q0(const float* __restrict__ U) {
    int n = blockIdx.x * blockDim.x + threadIdx.x;
    if (n >= NPIX) return;
    float nb = rsqrtf(g_rowsum[n]);
    g_nbi[n] = nb;
    float lg[LAB];
    float mx = -1e30f;
    #pragma unroll
    for (int l = 0; l < LAB; l++) {
        float v = -U[l * NPIX + n];
        lg[l] = v; mx = fmaxf(mx, v);
    }
    float se = 0.f;
    #pragma unroll
    for (int l = 0; l < LAB; l++) { lg[l] = __expf(lg[l] - mx); se += lg[l]; }
    float inv = 1.0f / se;
    #pragma unroll
    for (int l = 0; l < LAB; l++) {
        float q = lg[l] * inv;
        g_Q[l * NPIX + n] = q;
        g_VT[l * NPIX + n] = __float2half_rn(nb * q);
    }
}

// ===========================================================================
// Bilateral GEMM (fp16 HMMA) + fused spatial y-pass.
// C[9216,24] = K @ VT^T, K stored upper-tri; lower region consumed via
// ldmatrix.trans on the stored transposed tile. 144 CTAs x 64 rows.
// ===========================================================================
#define NS     6
#define NCH    144
#define STAGE  11264          // 8192 (A: 64x128B) + 3072 (B: 24x128B)
#define SMEM_BIL (NS * STAGE)

__device__ __forceinline__ void bil_load_stage(uint32_t base, int s,
                                               int rowBase, int c0, int tid,
                                               bool tr) {
    uint32_t sA = base + s * STAGE;
    uint32_t sB = sA + 8192;
    #pragma unroll
    for (int it = 0; it < 6; it++) {
        int u = tid + it * 128;             // 704 16B units total
        if (u < 512) {
            int r = u >> 3, j = u & 7;
            const __half* src = tr
                ? g_Kh + (size_t)(c0 + r) * NPIX + rowBase + j * 8
                : g_Kh + (size_t)(rowBase + r) * NPIX + c0 + j * 8;
            cp16(sA + swz(r * 128 + j * 16), src);
        } else if (u < 704) {
            int v = u - 512;
            int n = v >> 3, j = v & 7;
            cp16(sB + swz(n * 128 + j * 16),
                 g_VT + (size_t)n * NPIX + c0 + j * 8);
        }
    }
    asm volatile("cp.async.commit_group;" ::: "memory");
}

__global__ void __launch_bounds__(128, 1) k_bil() {
    extern __shared__ char smem[];
    uint32_t base = smem_u32(smem);
    int tid = threadIdx.x;
    int wid = tid >> 5, lane = tid & 31;
    int rowBase = blockIdx.x * 64;
    int myTile = rowBase >> 7;

    // lane geometry
    int ar = (lane & 7) + ((lane >> 3) & 1) * 8;     // direct: A row within 16
    int au = (lane >> 4) & 1;                        // direct: 16B unit along k
    int tr_row8 = ((lane >> 4) & 1) * 8 + (lane & 7);// trans: k row within 16
    int tr_colB = wid * 32 + ((lane >> 3) & 1) * 16; // trans: m byte col
    int bl = lane & 15;
    int brr = bl & 7;
    int bu = (bl >> 3) & 1;

    float d[3][4];
    #pragma unroll
    for (int t = 0; t < 3; t++)
        #pragma unroll
        for (int k = 0; k < 4; k++) d[t][k] = 0.f;

    #pragma unroll
    for (int j = 0; j < NS - 1; j++)
        bil_load_stage(base, j, rowBase, j * 64, tid, (j * 64 >> 7) < myTile);

    // ---- fused spatial y-pass (hides under cp.async streaming) ----
    {
        int stride = gridDim.x * blockDim.x;   // 18432
        for (int t = blockIdx.x * blockDim.x + tid; t < LAB * NPIX; t += stride) {
            int l = t / NPIX, n = t - l * NPIX;
            int y = n / WW, x = n - y * WW;
            float s = 0.f;
            #pragma unroll
            for (int dd = -RAD; dd <= RAD; dd++) {
                int yy = y + dd;
                if ((unsigned)yy < HH) {
                    int m = yy * WW + x;
                    s += g_kw[dd + RAD] * g_nsp[m] * g_Q[l * NPIX + m];
                }
            }
            g_tmp[t] = s;
        }
    }

    for (int i = 0; i < NCH; i++) {
        int rem = (NCH - 1) - i;
        if      (rem >= 4) asm volatile("cp.async.wait_group 4;" ::: "memory");
        else if (rem == 3) asm volatile("cp.async.wait_group 3;" ::: "memory");
        else if (rem == 2) asm volatile("cp.async.wait_group 2;" ::: "memory");
        else if (rem == 1) asm volatile("cp.async.wait_group 1;" ::: "memory");
        else               asm volatile("cp.async.wait_group 0;" ::: "memory");
        __syncthreads();

        uint32_t sA = base + (i % NS) * STAGE;
        uint32_t sB = sA + 8192;
        bool tr = ((i * 64) >> 7) < myTile;

        #pragma unroll
        for (int kk = 0; kk < 4; kk++) {
            uint32_t a0, a1, a2, a3;
            if (!tr) {
                uint32_t aoff = (uint32_t)((wid * 16 + ar) * 128 + (kk * 2 + au) * 16);
                asm volatile("ldmatrix.sync.aligned.m8n8.x4.shared.b16 {%0,%1,%2,%3}, [%4];"
                             : "=r"(a0), "=r"(a1), "=r"(a2), "=r"(a3)
                             : "r"(sA + swz(aoff)));
            } else {
                uint32_t aoff = (uint32_t)((kk * 16 + tr_row8) * 128 + tr_colB);
                asm volatile("ldmatrix.sync.aligned.m8n8.x4.trans.shared.b16 {%0,%1,%2,%3}, [%4];"
                             : "=r"(a0), "=r"(a1), "=r"(a2), "=r"(a3)
                             : "r"(sA + swz(aoff)));
            }
            #pragma unroll
            for (int t = 0; t < 3; t++) {
                uint32_t b0, b1;
                uint32_t boff = (uint32_t)((t * 8 + brr) * 128 + (kk * 2 + bu) * 16);
                asm volatile("ldmatrix.sync.aligned.m8n8.x2.shared.b16 {%0,%1}, [%2];"
                             : "=r"(b0), "=r"(b1)
                             : "r"(sB + swz(boff)));
                asm volatile("mma.sync.aligned.m16n8k16.row.col.f32.f16.f16.f32 "
                             "{%0,%1,%2,%3}, {%4,%5,%6,%7}, {%8,%9}, {%0,%1,%2,%3};"
                             : "+f"(d[t][0]), "+f"(d[t][1]), "+f"(d[t][2]), "+f"(d[t][3])
                             : "r"(a0), "r"(a1), "r"(a2), "r"(a3), "r"(b0), "r"(b1));
            }
        }
        __syncthreads();

        int n = i + NS - 1;
        if (n < NCH)
            bil_load_stage(base, n % NS, rowBase, n * 64, tid, ((n * 64) >> 7) < myTile);
    }

    int row = rowBase + wid * 16 + (lane >> 2);
    #pragma unroll
    for (int t = 0; t < 3; t++) {
        int col = t * 8 + (lane & 3) * 2;
        if (col < LAB)     g_C[row * LAB + col]           = d[t][0];
        if (col + 1 < LAB) g_C[row * LAB + col + 1]       = d[t][1];
        if (col < LAB)     g_C[(row + 8) * LAB + col]     = d[t][2];
        if (col + 1 < LAB) g_C[(row + 8) * LAB + col + 1] = d[t][3];
    }
}

// ===========================================================================
// Combine: x-conv of tmp, add unary + messages, softmax -> Q, VT
// ===========================================================================
__global__ void k_combine(const float* __restrict__ U, float* __restrict__ out,
                          int writeOut) {
    int n = blockIdx.x * blockDim.x + threadIdx.x;
    if (n >= NPIX) return;
    int y = n / WW, x = n - y * WW;
    float nsp = g_nsp[n];
    float nbi = g_nbi[n];

    float lg[LAB];
    float mx = -1e30f;
    #pragma unroll
    for (int l = 0; l < LAB; l++) {
        float s = 0.f;
        #pragma unroll
        for (int d = -RAD; d <= RAD; d++) {
            int xx = x + d;
            if ((unsigned)xx < WW)
                s += g_kw[d + RAD] * g_tmp[l * NPIX + y * WW + xx];
        }
        float v = -U[l * NPIX + n] + 3.0f * nsp * s + 10.0f * nbi * g_C[n * LAB + l];
        lg[l] = v; mx = fmaxf(mx, v);
    }
    float se = 0.f;
    #pragma unroll
    for (int l = 0; l < LAB; l++) { lg[l] = __expf(lg[l] - mx); se += lg[l]; }
    float inv = 1.0f / se;
    #pragma unroll
    for (int l = 0; l < LAB; l++) {
        float q = lg[l] * inv;
        g_Q[l * NPIX + n] = q;
        g_VT[l * NPIX + n] = __float2half_rn(nbi * q);
        if (writeOut) out[l * NPIX + n] = q;
    }
}

// ===========================================================================
extern "C" void kernel_launch(void* const* d_in, const int* in_sizes, int n_in,
                              void* d_out, int out_size) {
    const float* U = (const float*)d_in[0];   // [1,21,96,96]
    const float* I = (const float*)d_in[1];   // [1,3,96,96]
    float* out = (float*)d_out;               // [1,21,96,96]

    cudaFuncSetAttribute(k_bil, cudaFuncAttributeMaxDynamicSharedMemorySize, SMEM_BIL);

    k_prep<<<36, 256>>>(I);
    k_buildK<<<NBLK * (NBLK + 1) / 2, 256>>>();
    k_q0<<<36, 256>>>(U);

    for (int it = 0; it < 10; it++) {
        k_bil<<<NPIX / 64, 128, SMEM_BIL>>>();
        k_combine<<<36, 256>>>(U, out, it == 9 ? 1 : 0);
    }
}

// round 5
// speedup vs baseline: 5.4376x; 1.5363x over previous
#include <cuda_runtime.h>
#include <cuda_fp16.h>
#include <cstdint>

#define NPIX 9216
#define LAB  21
#define HH   96
#define WW   96
#define RAD  9
#define KWD  (2*RAD+1)
#define NBLK 72                 // 9216 / 128

// ---- scratch (device globals: allocation-free kernel_launch) ----
__device__ __half g_Kh[(size_t)NPIX * NPIX];   // only upper-tri 128-tiles written (~85MB touched)
__device__ float g_feats[NPIX * 5];
__device__ float g_rowsum[NPIX];
__device__ float g_nbi[NPIX];
__device__ float g_nsp[NPIX];
__device__ float g_kw[KWD];
__device__ float g_Q[LAB * NPIX];              // [L][N]
__device__ float g_tmp[LAB * NPIX];            // y-conv intermediate
__device__ __half g_VT[32 * NPIX];             // (nbi*Q)^T, rows 21..31 zero
__device__ float g_Cp[4 * NPIX * LAB];         // k-split partials of K @ V, [s][N][L]

// ===========================================================================
// helpers
// ===========================================================================
__device__ __forceinline__ uint32_t smem_u32(const void* p) {
    uint32_t a;
    asm("{ .reg .u64 t; cvta.to.shared.u64 t, %1; cvt.u32.u64 %0, t; }" : "=r"(a) : "l"(p));
    return a;
}
__device__ __forceinline__ uint32_t swz(uint32_t off) {   // 8x128B xor swizzle
    return off ^ ((off >> 3) & 0x70);
}
__device__ __forceinline__ void cp16(uint32_t dst, const void* src) {
    asm volatile("cp.async.cg.shared.global [%0], [%1], 16;" :: "r"(dst), "l"(src) : "memory");
}

// ===========================================================================
// Prep
// ===========================================================================
__global__ void k_prep(const float* __restrict__ I) {
    int n = blockIdx.x * blockDim.x + threadIdx.x;
    if (n >= NPIX) return;
    int y = n / WW, x = n % WW;

    if (n < KWD) {
        float d = (float)(n - RAD) / 3.0f;
        g_kw[n] = expf(-0.5f * d * d);
    }
    float sy = 0.f, sx = 0.f;
    #pragma unroll
    for (int d = -RAD; d <= RAD; d++) {
        float t = (float)d / 3.0f;
        float w = expf(-0.5f * t * t);
        if ((unsigned)(y + d) < HH) sy += w;
        if ((unsigned)(x + d) < WW) sx += w;
    }
    g_nsp[n] = rsqrtf(sy * sx);
    g_rowsum[n] = 0.f;

    g_feats[n * 5 + 0] = (float)x / 80.0f;
    g_feats[n * 5 + 1] = (float)y / 80.0f;
    g_feats[n * 5 + 2] = I[0 * NPIX + n] / 13.0f;
    g_feats[n * 5 + 3] = I[1 * NPIX + n] / 13.0f;
    g_feats[n * 5 + 4] = I[2 * NPIX + n] / 13.0f;

    __half z = __float2half(0.f);
    #pragma unroll
    for (int l = LAB; l < 32; l++) g_VT[l * NPIX + n] = z;
}

// ===========================================================================
// Build K (fp16), upper-triangle 128x128 tiles only. Row sums via atomics.
// ===========================================================================
#define TSTR 136
__global__ void __launch_bounds__(256) k_buildK() {
    __shared__ float fA[128 * 5];
    __shared__ float fB[128 * 5];
    __shared__ __align__(16) unsigned short tile[128 * TSTR];

    int id = blockIdx.x;
    int bi;
    {
        float b = 2.f * NBLK + 1.f;
        bi = (int)((b - sqrtf(b * b - 8.f * (float)id)) * 0.5f);
        if (bi < 0) bi = 0;
        if (bi > NBLK - 1) bi = NBLK - 1;
        while (bi * NBLK - bi * (bi - 1) / 2 > id) bi--;
        while ((bi + 1) * NBLK - (bi + 1) * bi / 2 <= id) bi++;
    }
    int bj = bi + (id - (bi * NBLK - bi * (bi - 1) / 2));

    int tid = threadIdx.x;
    for (int i = tid; i < 640; i += 256) {
        fA[i] = g_feats[bi * 640 + i];
        fB[i] = g_feats[bj * 640 + i];
    }
    __syncthreads();

    int r = tid >> 1;
    int cbase = (tid & 1) * 64;
    float f0 = fA[r * 5 + 0], f1 = fA[r * 5 + 1], f2 = fA[r * 5 + 2];
    float f3 = fA[r * 5 + 3], f4 = fA[r * 5 + 4];

    float sum = 0.f;
    #pragma unroll 4
    for (int c = 0; c < 64; c++) {
        const float* fb = &fB[(cbase + c) * 5];
        float t0 = f0 - fb[0], t1 = f1 - fb[1], t2 = f2 - fb[2];
        float t3 = f3 - fb[3], t4 = f4 - fb[4];
        float d = t0 * t0 + t1 * t1 + t2 * t2 + t3 * t3 + t4 * t4;
        float k = __expf(-0.5f * d);
        sum += k;
        tile[r * TSTR + cbase + c] = __half_as_ushort(__float2half_rn(k));
    }
    sum += __shfl_xor_sync(0xffffffffu, sum, 1);
    if ((tid & 1) == 0) atomicAdd(&g_rowsum[bi * 128 + r], sum);
    __syncthreads();

    unsigned short* gK = (unsigned short*)g_Kh;

    for (int o = tid * 8; o < 16384; o += 2048) {
        int rr = o >> 7, cc = o & 127;
        uint4 v = *(const uint4*)&tile[rr * TSTR + cc];
        *(uint4*)&gK[(size_t)(bi * 128 + rr) * NPIX + bj * 128 + cc] = v;
    }

    if (bi != bj) {
        if (tid < 128) {
            float s = 0.f;
            #pragma unroll 4
            for (int rr = 0; rr < 128; rr++)
                s += __half2float(__ushort_as_half(tile[rr * TSTR + tid]));
            atomicAdd(&g_rowsum[bj * 128 + tid], s);
        }
    }
}

// ===========================================================================
// Q0 = softmax(-U); nbi; seed VT
// ===========================================================================
__global__ void k_q0(const float* __restrict__ U) {
    int n = blockIdx.x * blockDim.x + threadIdx.x;
    if (n >= NPIX) return;
    float nb = rsqrtf(g_rowsum[n]);
    g_nbi[n] = nb;
    float lg[LAB];
    float mx = -1e30f;
    #pragma unroll
    for (int l = 0; l < LAB; l++) {
        float v = -U[l * NPIX + n];
        lg[l] = v; mx = fmaxf(mx, v);
    }
    float se = 0.f;
    #pragma unroll
    for (int l = 0; l < LAB; l++) { lg[l] = __expf(lg[l] - mx); se += lg[l]; }
    float inv = 1.0f / se;
    #pragma unroll
    for (int l = 0; l < LAB; l++) {
        float q = lg[l] * inv;
        g_Q[l * NPIX + n] = q;
        g_VT[l * NPIX + n] = __float2half_rn(nb * q);
    }
}

// ===========================================================================
// Bilateral GEMM (fp16 HMMA), 4-way k-split + fused spatial y-pass.
// 576 CTAs: (rowBlk 0..143) x (split 0..3). Each CTA: M=64 rows, 36 k-chunks
// of 64, writes partial C to g_Cp[split]. 4-stage cp.async pipeline -> 4
// CTAs/SM (45KB smem each) -> 16 warps/SM issuing LDGSTS.
// ===========================================================================
#define KSPLIT 4
#define NS     4
#define NCHS   36            // 144 / KSPLIT
#define STAGE  11264         // 8192 (A: 64x128B) + 3072 (B: 24x128B)
#define SMEM_BIL (NS * STAGE)

__device__ __forceinline__ void bil_load_stage(uint32_t base, int s,
                                               int rowBase, int c0, int tid,
                                               bool tr) {
    uint32_t sA = base + s * STAGE;
    uint32_t sB = sA + 8192;
    #pragma unroll
    for (int it = 0; it < 6; it++) {
        int u = tid + it * 128;             // 704 16B units total
        if (u < 512) {
            int r = u >> 3, j = u & 7;
            const __half* src = tr
                ? g_Kh + (size_t)(c0 + r) * NPIX + rowBase + j * 8
                : g_Kh + (size_t)(rowBase + r) * NPIX + c0 + j * 8;
            cp16(sA + swz(r * 128 + j * 16), src);
        } else if (u < 704) {
            int v = u - 512;
            int n = v >> 3, j = v & 7;
            cp16(sB + swz(n * 128 + j * 16),
                 g_VT + (size_t)n * NPIX + c0 + j * 8);
        }
    }
    asm volatile("cp.async.commit_group;" ::: "memory");
}

__global__ void __launch_bounds__(128, 4) k_bil() {
    extern __shared__ char smem[];
    uint32_t base = smem_u32(smem);
    int tid = threadIdx.x;
    int wid = tid >> 5, lane = tid & 31;
    int split = blockIdx.x & (KSPLIT - 1);
    int rowBase = (blockIdx.x >> 2) * 64;
    int myTile = rowBase >> 7;
    int c0base = split * NCHS * 64;

    // lane geometry
    int ar = (lane & 7) + ((lane >> 3) & 1) * 8;
    int au = (lane >> 4) & 1;
    int tr_row8 = ((lane >> 4) & 1) * 8 + (lane & 7);
    int tr_colB = wid * 32 + ((lane >> 3) & 1) * 16;
    int bl = lane & 15;
    int brr = bl & 7;
    int bu = (bl >> 3) & 1;

    float d[3][4];
    #pragma unroll
    for (int t = 0; t < 3; t++)
        #pragma unroll
        for (int k = 0; k < 4; k++) d[t][k] = 0.f;

    #pragma unroll
    for (int j = 0; j < NS - 1; j++) {
        int c0 = c0base + j * 64;
        bil_load_stage(base, j, rowBase, c0, tid, (c0 >> 7) < myTile);
    }

    // ---- fused spatial y-pass (hides under cp.async streaming) ----
    {
        int stride = gridDim.x * blockDim.x;
        for (int t = blockIdx.x * blockDim.x + tid; t < LAB * NPIX; t += stride) {
            int l = t / NPIX, n = t - l * NPIX;
            int y = n / WW, x = n - y * WW;
            float s = 0.f;
            #pragma unroll
            for (int dd = -RAD; dd <= RAD; dd++) {
                int yy = y + dd;
                if ((unsigned)yy < HH) {
                    int m = yy * WW + x;
                    s += g_kw[dd + RAD] * g_nsp[m] * g_Q[l * NPIX + m];
                }
            }
            g_tmp[t] = s;
        }
    }

    for (int i = 0; i < NCHS; i++) {
        int rem = (NCHS - 1) - i;
        if      (rem >= 2) asm volatile("cp.async.wait_group 2;" ::: "memory");
        else if (rem == 1) asm volatile("cp.async.wait_group 1;" ::: "memory");
        else               asm volatile("cp.async.wait_group 0;" ::: "memory");
        __syncthreads();

        uint32_t sA = base + (i % NS) * STAGE;
        uint32_t sB = sA + 8192;
        int c0 = c0base + i * 64;
        bool tr = (c0 >> 7) < myTile;

        #pragma unroll
        for (int kk = 0; kk < 4; kk++) {
            uint32_t a0, a1, a2, a3;
            if (!tr) {
                uint32_t aoff = (uint32_t)((wid * 16 + ar) * 128 + (kk * 2 + au) * 16);
                asm volatile("ldmatrix.sync.aligned.m8n8.x4.shared.b16 {%0,%1,%2,%3}, [%4];"
                             : "=r"(a0), "=r"(a1), "=r"(a2), "=r"(a3)
                             : "r"(sA + swz(aoff)));
            } else {
                uint32_t aoff = (uint32_t)((kk * 16 + tr_row8) * 128 + tr_colB);
                asm volatile("ldmatrix.sync.aligned.m8n8.x4.trans.shared.b16 {%0,%1,%2,%3}, [%4];"
                             : "=r"(a0), "=r"(a1), "=r"(a2), "=r"(a3)
                             : "r"(sA + swz(aoff)));
            }
            #pragma unroll
            for (int t = 0; t < 3; t++) {
                uint32_t b0, b1;
                uint32_t boff = (uint32_t)((t * 8 + brr) * 128 + (kk * 2 + bu) * 16);
                asm volatile("ldmatrix.sync.aligned.m8n8.x2.shared.b16 {%0,%1}, [%2];"
                             : "=r"(b0), "=r"(b1)
                             : "r"(sB + swz(boff)));
                asm volatile("mma.sync.aligned.m16n8k16.row.col.f32.f16.f16.f32 "
                             "{%0,%1,%2,%3}, {%4,%5,%6,%7}, {%8,%9}, {%0,%1,%2,%3};"
                             : "+f"(d[t][0]), "+f"(d[t][1]), "+f"(d[t][2]), "+f"(d[t][3])
                             : "r"(a0), "r"(a1), "r"(a2), "r"(a3), "r"(b0), "r"(b1));
            }
        }
        __syncthreads();

        int n = i + NS - 1;
        if (n < NCHS) {
            int nc0 = c0base + n * 64;
            bil_load_stage(base, n % NS, rowBase, nc0, tid, (nc0 >> 7) < myTile);
        }
    }

    float* Cp = g_Cp + (size_t)split * NPIX * LAB;
    int row = rowBase + wid * 16 + (lane >> 2);
    #pragma unroll
    for (int t = 0; t < 3; t++) {
        int col = t * 8 + (lane & 3) * 2;
        if (col < LAB)     Cp[row * LAB + col]           = d[t][0];
        if (col + 1 < LAB) Cp[row * LAB + col + 1]       = d[t][1];
        if (col < LAB)     Cp[(row + 8) * LAB + col]     = d[t][2];
        if (col + 1 < LAB) Cp[(row + 8) * LAB + col + 1] = d[t][3];
    }
}

// ===========================================================================
// Combine: x-conv of tmp, sum k-split partials, unary + messages, softmax
// ===========================================================================
__global__ void k_combine(const float* __restrict__ U, float* __restrict__ out,
                          int writeOut) {
    int n = blockIdx.x * blockDim.x + threadIdx.x;
    if (n >= NPIX) return;
    int y = n / WW, x = n - y * WW;
    float nsp = g_nsp[n];
    float nbi = g_nbi[n];

    float lg[LAB];
    float mx = -1e30f;
    #pragma unroll
    for (int l = 0; l < LAB; l++) {
        float s = 0.f;
        #pragma unroll
        for (int d = -RAD; d <= RAD; d++) {
            int xx = x + d;
            if ((unsigned)xx < WW)
                s += g_kw[d + RAD] * g_tmp[l * NPIX + y * WW + xx];
        }
        float c = g_Cp[n * LAB + l]
                + g_Cp[1 * NPIX * LAB + n * LAB + l]
                + g_Cp[2 * NPIX * LAB + n * LAB + l]
                + g_Cp[3 * NPIX * LAB + n * LAB + l];
        float v = -U[l * NPIX + n] + 3.0f * nsp * s + 10.0f * nbi * c;
        lg[l] = v; mx = fmaxf(mx, v);
    }
    float se = 0.f;
    #pragma unroll
    for (int l = 0; l < LAB; l++) { lg[l] = __expf(lg[l] - mx); se += lg[l]; }
    float inv = 1.0f / se;
    #pragma unroll
    for (int l = 0; l < LAB; l++) {
        float q = lg[l] * inv;
        g_Q[l * NPIX + n] = q;
        g_VT[l * NPIX + n] = __float2half_rn(nbi * q);
        if (writeOut) out[l * NPIX + n] = q;
    }
}

// ===========================================================================
extern "C" void kernel_launch(void* const* d_in, const int* in_sizes, int n_in,
                              void* d_out, int out_size) {
    const float* U = (const float*)d_in[0];   // [1,21,96,96]
    const float* I = (const float*)d_in[1];   // [1,3,96,96]
    float* out = (float*)d_out;               // [1,21,96,96]

    cudaFuncSetAttribute(k_bil, cudaFuncAttributeMaxDynamicSharedMemorySize, SMEM_BIL);

    k_prep<<<36, 256>>>(I);
    k_buildK<<<NBLK * (NBLK + 1) / 2, 256>>>();
    k_q0<<<36, 256>>>(U);

    for (int it = 0; it < 10; it++) {
        k_bil<<<(NPIX / 64) * KSPLIT, 128, SMEM_BIL>>>();
        k_combine<<<36, 256>>>(U, out, it == 9 ? 1 : 0);
    }
}